// round 2
// baseline (speedup 1.0000x reference)
#include <cuda_runtime.h>

#define N_NODES 50000
#define N_EDGES 800000
#define IN_F 96
#define HID 64
#define N_CLS 32

// Scratch (allocation-free rule: __device__ globals)
__device__ __align__(16) float g_agg1[N_NODES * IN_F];   // 19.2 MB
__device__ __align__(16) float g_h[N_NODES * HID];       // 12.8 MB
__device__ __align__(16) float g_agg2[N_NODES * HID];    // 12.8 MB

__device__ __forceinline__ void red_add_v4(float* p, float4 v) {
    asm volatile("red.global.add.v4.f32 [%0], {%1,%2,%3,%4};"
                 :: "l"(p), "f"(v.x), "f"(v.y), "f"(v.z), "f"(v.w) : "memory");
}

__global__ void zero_kernel() {
    const int n1 = N_NODES * IN_F / 4;
    const int n2 = N_NODES * HID / 4;
    float4* a = (float4*)g_agg1;
    float4* b = (float4*)g_agg2;
    int stride = gridDim.x * blockDim.x;
    for (int i = blockIdx.x * blockDim.x + threadIdx.x; i < n1 + n2; i += stride) {
        if (i < n1) a[i] = make_float4(0.f, 0.f, 0.f, 0.f);
        else        b[i - n1] = make_float4(0.f, 0.f, 0.f, 0.f);
    }
}

// Scatter-add of C float4 chunks per edge: out[dst] += feat[src]
template <int C>
__global__ void scatter_kernel(const float4* __restrict__ feat,
                               float* __restrict__ out,
                               const int* __restrict__ src,
                               const int* __restrict__ dst) {
    long long total = (long long)N_EDGES * C;
    long long stride = (long long)gridDim.x * blockDim.x;
    for (long long i = blockIdx.x * (long long)blockDim.x + threadIdx.x;
         i < total; i += stride) {
        int e = (int)(i / C);
        int c = (int)(i - (long long)e * C);
        int s = src[e];
        int d = dst[e];
        float4 v = feat[(long long)s * C + c];
        red_add_v4(out + (long long)d * (4 * C) + 4 * c, v);
    }
}

// h = relu(agg1 @ W1 + b1).  blockDim=256 => 4 nodes/block, thread j computes h[n][j].
__global__ void gemm1_relu_kernel(const float* __restrict__ A,
                                  const float* __restrict__ W1,
                                  const float* __restrict__ b1,
                                  float* __restrict__ H) {
    __shared__ float Ws[IN_F * HID];
    for (int i = threadIdx.x; i < IN_F * HID; i += blockDim.x) Ws[i] = W1[i];
    __syncthreads();
    int j = threadIdx.x & (HID - 1);
    int n = blockIdx.x * 4 + (threadIdx.x >> 6);
    if (n >= N_NODES) return;
    const float* a = A + (long long)n * IN_F;
    float acc = b1[j];
#pragma unroll 8
    for (int k = 0; k < IN_F; ++k) acc = fmaf(a[k], Ws[k * HID + j], acc);
    H[(long long)n * HID + j] = fmaxf(acc, 0.f);
}

// out = log_softmax(agg2 @ W2 + b2).  One warp per node, lane = class.
__global__ void gemm2_lsm_kernel(const float* __restrict__ A,
                                 const float* __restrict__ W2,
                                 const float* __restrict__ b2,
                                 float* __restrict__ out) {
    __shared__ float Ws[HID * N_CLS];
    __shared__ float bs[N_CLS];
    for (int i = threadIdx.x; i < HID * N_CLS; i += blockDim.x) Ws[i] = W2[i];
    if (threadIdx.x < N_CLS) bs[threadIdx.x] = b2[threadIdx.x];
    __syncthreads();
    int lane = threadIdx.x & 31;
    int n = blockIdx.x * 8 + (threadIdx.x >> 5);
    if (n >= N_NODES) return;
    const float* a = A + (long long)n * HID;
    float acc = bs[lane];
#pragma unroll
    for (int k = 0; k < HID; ++k) acc = fmaf(a[k], Ws[k * N_CLS + lane], acc);
    // warp-level log_softmax over 32 classes (one per lane)
    float m = acc;
#pragma unroll
    for (int o = 16; o; o >>= 1) m = fmaxf(m, __shfl_xor_sync(0xffffffffu, m, o));
    float p = __expf(acc - m);
#pragma unroll
    for (int o = 16; o; o >>= 1) p += __shfl_xor_sync(0xffffffffu, p, o);
    out[(long long)n * N_CLS + lane] = acc - m - __logf(p);
}

extern "C" void kernel_launch(void* const* d_in, const int* in_sizes, int n_in,
                              void* d_out, int out_size) {
    const float* x   = (const float*)d_in[0];
    const int*   ei  = (const int*)d_in[1];   // edge_index downcast to int32, [2, E]
    const float* W1  = (const float*)d_in[2];
    const float* b1  = (const float*)d_in[3];
    const float* W2  = (const float*)d_in[4];
    const float* b2  = (const float*)d_in[5];
    float* out       = (float*)d_out;

    const int* src = ei;
    const int* dst = ei + N_EDGES;

    float* agg1; cudaGetSymbolAddress((void**)&agg1, g_agg1);
    float* h;    cudaGetSymbolAddress((void**)&h,    g_h);
    float* agg2; cudaGetSymbolAddress((void**)&agg2, g_agg2);

    // 1. zero accumulators
    zero_kernel<<<1184, 256>>>();

    // 2. agg1[dst] += x[src]  (96 floats = 24 float4 per edge)
    {
        long long total = (long long)N_EDGES * 24;
        int blocks = (int)((total + 255) / 256);
        scatter_kernel<24><<<blocks, 256>>>((const float4*)x, agg1, src, dst);
    }

    // 3. h = relu(agg1 @ W1 + b1)
    gemm1_relu_kernel<<<(N_NODES + 3) / 4, 256>>>(agg1, W1, b1, h);

    // 4. agg2[dst] += h[src]  (64 floats = 16 float4 per edge)
    {
        long long total = (long long)N_EDGES * 16;
        int blocks = (int)((total + 255) / 256);
        scatter_kernel<16><<<blocks, 256>>>((const float4*)h, agg2, src, dst);
    }

    // 5. out = log_softmax(agg2 @ W2 + b2)
    gemm2_lsm_kernel<<<(N_NODES + 7) / 8, 256>>>(agg2, W2, b2, out);
}

// round 3
// speedup vs baseline: 1.4284x; 1.4284x over previous
#include <cuda_runtime.h>

#define N_NODES 50000
#define N_EDGES 800000
#define IN_F 96
#define HID 64
#define N_CLS 32

// Scratch (allocation-free rule: __device__ globals)
__device__ __align__(16) float g_y[N_NODES * HID];       // x @ W1        (12.8 MB)
__device__ __align__(16) float g_agg1[N_NODES * HID];    // scatter of y  (12.8 MB)
__device__ __align__(16) float g_z[N_NODES * N_CLS];     // relu(..)@W2   ( 6.4 MB)
__device__ __align__(16) float g_agg2[N_NODES * N_CLS];  // scatter of z  ( 6.4 MB)

__device__ __forceinline__ void red_add_v4(float* p, float4 v) {
    asm volatile("red.global.add.v4.f32 [%0], {%1,%2,%3,%4};"
                 :: "l"(p), "f"(v.x), "f"(v.y), "f"(v.z), "f"(v.w) : "memory");
}

// Zero agg1 (50000*64) + agg2 (50000*32) = 1.2M float4
__global__ void zero_kernel() {
    const int n1 = N_NODES * HID / 4;
    const int n2 = N_NODES * N_CLS / 4;
    int i = blockIdx.x * blockDim.x + threadIdx.x;
    float4 zv = make_float4(0.f, 0.f, 0.f, 0.f);
    if (i < n1) ((float4*)g_agg1)[i] = zv;
    else if (i < n1 + n2) ((float4*)g_agg2)[i - n1] = zv;
}

// y = x @ W1  [50000 x 64], no bias. 4 nodes per 256-thread block.
__global__ void gemm_x_kernel(const float* __restrict__ x,
                              const float* __restrict__ W1,
                              float* __restrict__ Y) {
    __shared__ float Ws[IN_F * HID];
    for (int i = threadIdx.x; i < IN_F * HID; i += 256) Ws[i] = W1[i];
    __syncthreads();
    int j = threadIdx.x & (HID - 1);
    int n = blockIdx.x * 4 + (threadIdx.x >> 6);
    const float* a = x + n * IN_F;
    float acc = 0.f;
#pragma unroll
    for (int k = 0; k < IN_F; ++k) acc = fmaf(__ldg(a + k), Ws[k * HID + j], acc);
    Y[n * HID + j] = acc;
}

// Scatter-add: out[dst] += feat[src], C float4 chunks per edge, C = 1<<LOGC.
template <int LOGC>
__global__ void scatter_kernel(const float4* __restrict__ feat,
                               float* __restrict__ out,
                               const int* __restrict__ src,
                               const int* __restrict__ dst) {
    const int C = 1 << LOGC;
    int i = blockIdx.x * blockDim.x + threadIdx.x;
    int e = i >> LOGC;
    int c = i & (C - 1);
    int s = __ldg(src + e);
    int d = __ldg(dst + e);
    float4 v = __ldg(feat + s * C + c);
    red_add_v4(out + d * (4 * C) + 4 * c, v);
}

// z = relu(agg1 + b1) @ W2  [50000 x 32]. One warp per node, 8 nodes/block.
__global__ void hidden_kernel(const float* __restrict__ agg1,
                              const float* __restrict__ b1,
                              const float* __restrict__ W2,
                              float* __restrict__ Z) {
    __shared__ float Ws[HID * N_CLS];
    __shared__ float hs[8][HID];
    for (int i = threadIdx.x; i < HID * N_CLS; i += 256) Ws[i] = W2[i];
    __syncthreads();
    int lane = threadIdx.x & 31;
    int w = threadIdx.x >> 5;
    int n = blockIdx.x * 8 + w;
    const float* a = agg1 + n * HID;
    hs[w][lane]      = fmaxf(a[lane]      + __ldg(b1 + lane),      0.f);
    hs[w][lane + 32] = fmaxf(a[lane + 32] + __ldg(b1 + lane + 32), 0.f);
    __syncwarp();
    float acc = 0.f;
#pragma unroll
    for (int k = 0; k < HID; ++k) acc = fmaf(hs[w][k], Ws[k * N_CLS + lane], acc);
    Z[n * N_CLS + lane] = acc;
}

// out = log_softmax(agg2 + b2). One warp per node (lane = class), 8 nodes/block.
__global__ void lsm_kernel(const float* __restrict__ agg2,
                           const float* __restrict__ b2,
                           float* __restrict__ out) {
    int lane = threadIdx.x & 31;
    int n = blockIdx.x * 8 + (threadIdx.x >> 5);
    float acc = agg2[n * N_CLS + lane] + __ldg(b2 + lane);
    float m = acc;
#pragma unroll
    for (int o = 16; o; o >>= 1) m = fmaxf(m, __shfl_xor_sync(0xffffffffu, m, o));
    float p = __expf(acc - m);
#pragma unroll
    for (int o = 16; o; o >>= 1) p += __shfl_xor_sync(0xffffffffu, p, o);
    out[n * N_CLS + lane] = acc - m - __logf(p);
}

extern "C" void kernel_launch(void* const* d_in, const int* in_sizes, int n_in,
                              void* d_out, int out_size) {
    const float* x   = (const float*)d_in[0];
    const int*   ei  = (const int*)d_in[1];   // edge_index as int32, [2, E]
    const float* W1  = (const float*)d_in[2];
    const float* b1  = (const float*)d_in[3];
    const float* W2  = (const float*)d_in[4];
    const float* b2  = (const float*)d_in[5];
    float* out       = (float*)d_out;

    const int* src = ei;
    const int* dst = ei + N_EDGES;

    float* y;    cudaGetSymbolAddress((void**)&y,    g_y);
    float* agg1; cudaGetSymbolAddress((void**)&agg1, g_agg1);
    float* z;    cudaGetSymbolAddress((void**)&z,    g_z);
    float* agg2; cudaGetSymbolAddress((void**)&agg2, g_agg2);

    // 1. zero accumulators (1.2M float4)
    zero_kernel<<<(N_NODES * (HID + N_CLS) / 4 + 255) / 256, 256>>>();

    // 2. y = x @ W1
    gemm_x_kernel<<<N_NODES / 4, 256>>>(x, W1, y);

    // 3. agg1[dst] += y[src]   (64 floats = 16 float4 per edge)
    scatter_kernel<4><<<N_EDGES * 16 / 256, 256>>>((const float4*)y, agg1, src, dst);

    // 4. z = relu(agg1 + b1) @ W2
    hidden_kernel<<<N_NODES / 8, 256>>>(agg1, b1, W2, z);

    // 5. agg2[dst] += z[src]   (32 floats = 8 float4 per edge)
    scatter_kernel<3><<<N_EDGES * 8 / 256, 256>>>((const float4*)z, agg2, src, dst);

    // 6. out = log_softmax(agg2 + b2)
    lsm_kernel<<<N_NODES / 8, 256>>>(agg2, b2, out);
}